// round 2
// baseline (speedup 1.0000x reference)
#include <cuda_runtime.h>

// Reference analysis:
//   attention = softmax(const(-9e15)) == uniform 1/N   (adj, a, e are dead code)
//   out[i,f]  = relu( (colsum(h) @ W)[f] / N )  -- identical row broadcast N times.
//
// Real work: 16MB read of h + tiny (512x64) GEMV + 2MB broadcast write.

#define N_ROWS 8192
#define F_IN   512
#define F_OUT  64
#define CHUNKS 256
#define ROWS_PER_CHUNK (N_ROWS / CHUNKS)   // 32

// Scratch (static device globals -- allocation-free per harness rules)
__device__ float g_partial[CHUNKS * F_IN];   // 512 KB partial column sums
__device__ float g_row[F_OUT];               // final broadcast row

// K1: deterministic partial column sums of h.
// Block b sums rows [b*32, b*32+32). 128 threads, each owns 4 contiguous
// columns via float4 (warp covers 512 contiguous bytes per row -> coalesced).
__global__ __launch_bounds__(128)
void colsum_partial_kernel(const float4* __restrict__ h4) {
    const int c4    = threadIdx.x;           // 0..127 (float4 column group)
    const int chunk = blockIdx.x;            // 0..255
    const float4* base = h4 + (size_t)chunk * ROWS_PER_CHUNK * (F_IN / 4) + c4;
    float4 acc = make_float4(0.f, 0.f, 0.f, 0.f);
#pragma unroll
    for (int r = 0; r < ROWS_PER_CHUNK; ++r) {
        float4 v = base[(size_t)r * (F_IN / 4)];
        acc.x += v.x; acc.y += v.y; acc.z += v.z; acc.w += v.w;
    }
    reinterpret_cast<float4*>(g_partial)[chunk * (F_IN / 4) + c4] = acc;  // fixed order
}

// K2: reduce 256 partials per column (fixed order), then project through W,
// scale by 1/N, relu. Single block, 512 threads.
__global__ __launch_bounds__(F_IN)
void reduce_project_kernel(const float* __restrict__ W) {
    __shared__ float s[F_IN];
    const int col = threadIdx.x;             // 0..511
    float acc = 0.0f;
#pragma unroll 8
    for (int c = 0; c < CHUNKS; ++c) {
        acc += g_partial[c * F_IN + col];
    }
    s[col] = acc;
    __syncthreads();

    if (col < F_OUT) {
        float o = 0.0f;
#pragma unroll 8
        for (int k = 0; k < F_IN; ++k) {
            o = fmaf(s[k], W[k * F_OUT + col], o);   // W (512,64) row-major: coalesced across threads
        }
        o *= (1.0f / (float)N_ROWS);
        g_row[col] = fmaxf(o, 0.0f);
    }
}

// K3: broadcast the 64-float row to all 8192 output rows.
// 8192*64 floats = 131072 float4 stores; 512 blocks x 256 threads, 1 store each.
__global__ __launch_bounds__(256)
void broadcast_kernel(float4* __restrict__ out) {
    __shared__ float4 rowv[F_OUT / 4];       // 16 float4 = one output row
    if (threadIdx.x < F_OUT / 4) {
        rowv[threadIdx.x] = reinterpret_cast<const float4*>(g_row)[threadIdx.x];
    }
    __syncthreads();
    const int i = blockIdx.x * blockDim.x + threadIdx.x;   // 0..131071
    out[i] = rowv[i & (F_OUT / 4 - 1)];                    // i mod 16 -> column group
}

extern "C" void kernel_launch(void* const* d_in, const int* in_sizes, int n_in,
                              void* d_out, int out_size) {
    (void)in_sizes; (void)n_in; (void)out_size;
    const float* h = (const float*)d_in[0];   // (8192, 512) fp32
    // d_in[1] = adj (8192,8192)  -- dead code in reference, never read
    const float* W = (const float*)d_in[2];   // (512, 64) fp32
    // d_in[3] = a (128,1)        -- dead code in reference, never read
    float* out = (float*)d_out;               // (8192, 64) fp32

    colsum_partial_kernel<<<CHUNKS, 128>>>((const float4*)h);
    reduce_project_kernel<<<1, F_IN>>>(W);
    broadcast_kernel<<<(N_ROWS * F_OUT / 4) / 256, 256>>>((float4*)out);
}